// round 3
// baseline (speedup 1.0000x reference)
#include <cuda_runtime.h>

#define BM 128
#define BN 128
#define BK 16
#define NT 256

// Fused TensorProductRescale:
//   region 0            : out0 (N=256, K=384)  A = [x0*y0 | d],      W = [SQK0*w000 ; SQK0*IS3*w110]
//   region i (i0=0..2)  : out1[:,:,i0] (N=128, K=512)
//                         A = [x0*y1_i | x1_i*y0 | cr_i], W = [SQK1*w011 ; SQK1*w101 ; SQK1*IS2*w111]
__global__ void __launch_bounds__(NT, 2)
tpr_kernel(const float* __restrict__ x, const float* __restrict__ y,
           const float* __restrict__ w000, const float* __restrict__ w110,
           const float* __restrict__ w011, const float* __restrict__ w101,
           const float* __restrict__ w111, const float* __restrict__ b0,
           float* __restrict__ out, int B)
{
    const float SQK0 = 0.05103103630798288f;   // 1/sqrt(384)
    const float SQK1 = 0.04419417382415922f;   // 1/sqrt(512)
    const float IS3  = 0.57735026918962584f;   // 1/sqrt(3)
    const float IS2  = 0.70710678118654752f;   // 1/sqrt(2)

    __shared__ float As[BK][BM + 1];   // +1 pad: conflict-free k-strided writes
    __shared__ float Ws[BK][BN];
    __shared__ float ys[BM][4];

    const int job  = blockIdx.x;           // 0,1 -> region0 colblock; 2,3,4 -> region 1..3
    const int row0 = blockIdx.y * BM;
    const int tid  = threadIdx.x;
    const int tx   = tid & 15;             // col group (8 cols each)
    const int ty   = tid >> 4;             // row group (8 strided rows each)
    const int nb   = tx * 8;

    int region, cb;
    if (job < 2) { region = 0; cb = job; } else { region = job - 1; cb = 0; }
    const int i0 = region - 1;             // only meaningful when region > 0
    const int j1 = (i0 + 1) % 3;
    const int j2 = (i0 + 2) % 3;

    // load y tile
    for (int i = tid; i < BM * 4; i += NT) {
        int m = i >> 2, c = i & 3;
        int r = row0 + m;
        ys[m][c] = (r < B) ? y[(size_t)r * 4 + c] : 0.0f;
    }

    float acc[8][8];
    #pragma unroll
    for (int r = 0; r < 8; r++)
        #pragma unroll
        for (int c = 0; c < 8; c++) acc[r][c] = 0.0f;

    const int KT  = (region == 0) ? 24 : 32;   // K/BK
    const int fm  = tid >> 1;                  // feature row handled by this thread
    const int fkb = (tid & 1) * 8;             // feature k sub-block (0 or 8)
    const int frow = row0 + fm;
    const float* xr = x + (size_t)frow * 640;

    __syncthreads();   // ys ready

    for (int kt = 0; kt < KT; kt++) {
        const int k0 = kt * BK;

        // ---- stage weight tile (scales folded) ----
        #pragma unroll
        for (int r = 0; r < 2; r++) {
            int idx = tid + r * NT;        // float4 index within 16x128 tile
            int kw  = idx >> 5;            // 0..15
            int col = (idx & 31) * 4;
            int kg  = k0 + kw;
            const float* src; float s;
            if (region == 0) {
                if (kg < 256) { src = w000 + (size_t)kg * 256 + cb * 128 + col;        s = SQK0; }
                else          { src = w110 + (size_t)(kg - 256) * 256 + cb * 128 + col; s = SQK0 * IS3; }
            } else {
                if (kg < 256)      { src = w011 + (size_t)kg * 128 + col;         s = SQK1; }
                else if (kg < 384) { src = w101 + (size_t)(kg - 256) * 128 + col; s = SQK1; }
                else               { src = w111 + (size_t)(kg - 384) * 128 + col; s = SQK1 * IS2; }
            }
            float4 v = *(const float4*)src;
            v.x *= s; v.y *= s; v.z *= s; v.w *= s;
            *(float4*)&Ws[kw][col] = v;
        }

        // ---- stage feature tile (computed on the fly) ----
        float f[8];
        if (frow < B) {
            float yv0 = ys[fm][0], yv1 = ys[fm][1], yv2 = ys[fm][2], yv3 = ys[fm][3];
            if (k0 < 256) {
                float sc = (region == 0) ? yv0 : ys[fm][1 + i0];
                const float4* p = (const float4*)(xr + k0 + fkb);
                float4 a0 = p[0], a1 = p[1];
                f[0] = a0.x * sc; f[1] = a0.y * sc; f[2] = a0.z * sc; f[3] = a0.w * sc;
                f[4] = a1.x * sc; f[5] = a1.y * sc; f[6] = a1.z * sc; f[7] = a1.w * sc;
            } else {
                int u0, mode;                   // 0: d, 1: x1_i*y0, 2: cross
                if (region == 0)   { u0 = k0 - 256 + fkb; mode = 0; }
                else if (k0 < 384) { u0 = k0 - 256 + fkb; mode = 1; }
                else               { u0 = k0 - 384 + fkb; mode = 2; }
                const float4* p = (const float4*)(xr + 256 + 3 * u0);
                float v[24];
                #pragma unroll
                for (int q = 0; q < 6; q++) *(float4*)&v[4 * q] = p[q];
                #pragma unroll
                for (int jj = 0; jj < 8; jj++) {
                    float e0 = v[3 * jj], e1 = v[3 * jj + 1], e2 = v[3 * jj + 2];
                    if (mode == 0) {
                        f[jj] = e0 * yv1 + e1 * yv2 + e2 * yv3;          // d[u]
                    } else if (mode == 1) {
                        float xi = (i0 == 0) ? e0 : ((i0 == 1) ? e1 : e2);
                        f[jj] = xi * yv0;                                 // x1_i * y0
                    } else {
                        // cr_i = x1_{j1} * y1_{j2} - x1_{j2} * y1_{j1}
                        float xa = (j1 == 0) ? e0 : ((j1 == 1) ? e1 : e2);
                        float xb = (j2 == 0) ? e0 : ((j2 == 1) ? e1 : e2);
                        float ya = (j2 == 0) ? yv1 : ((j2 == 1) ? yv2 : yv3);
                        float yb = (j1 == 0) ? yv1 : ((j1 == 1) ? yv2 : yv3);
                        f[jj] = xa * ya - xb * yb;
                    }
                }
            }
        } else {
            #pragma unroll
            for (int jj = 0; jj < 8; jj++) f[jj] = 0.0f;
        }
        #pragma unroll
        for (int jj = 0; jj < 8; jj++) As[fkb + jj][fm] = f[jj];

        __syncthreads();

        // ---- compute ----
        #pragma unroll
        for (int k = 0; k < BK; k++) {
            float a[8];
            #pragma unroll
            for (int r = 0; r < 8; r++) a[r] = As[k][ty + 16 * r];
            float4 w0 = *(const float4*)&Ws[k][nb];
            float4 w1 = *(const float4*)&Ws[k][nb + 4];
            float w[8] = {w0.x, w0.y, w0.z, w0.w, w1.x, w1.y, w1.z, w1.w};
            #pragma unroll
            for (int r = 0; r < 8; r++)
                #pragma unroll
                for (int c = 0; c < 8; c++)
                    acc[r][c] = fmaf(a[r], w[c], acc[r][c]);
        }

        __syncthreads();
    }

    // ---- epilogue ----
    if (region == 0) {
        float4 bv0 = *(const float4*)&b0[cb * 128 + nb];
        float4 bv1 = *(const float4*)&b0[cb * 128 + nb + 4];
        #pragma unroll
        for (int r = 0; r < 8; r++) {
            int row = row0 + ty + 16 * r;
            if (row < B) {
                float* o = out + (size_t)row * 640 + cb * 128 + nb;
                float4 s0 = make_float4(acc[r][0] + bv0.x, acc[r][1] + bv0.y,
                                        acc[r][2] + bv0.z, acc[r][3] + bv0.w);
                float4 s1 = make_float4(acc[r][4] + bv1.x, acc[r][5] + bv1.y,
                                        acc[r][6] + bv1.z, acc[r][7] + bv1.w);
                *(float4*)o       = s0;
                *(float4*)(o + 4) = s1;
            }
        }
    } else {
        #pragma unroll
        for (int r = 0; r < 8; r++) {
            int row = row0 + ty + 16 * r;
            if (row < B) {
                float* o = out + (size_t)row * 640 + 256 + i0;
                #pragma unroll
                for (int c = 0; c < 8; c++)
                    o[(nb + c) * 3] = acc[r][c];   // out1 layout: 256 + w*3 + i
            }
        }
    }
}

extern "C" void kernel_launch(void* const* d_in, const int* in_sizes, int n_in,
                              void* d_out, int out_size)
{
    const float* x    = (const float*)d_in[0];
    const float* y    = (const float*)d_in[1];
    const float* w000 = (const float*)d_in[2];
    const float* w110 = (const float*)d_in[3];
    const float* w011 = (const float*)d_in[4];
    const float* w101 = (const float*)d_in[5];
    const float* w111 = (const float*)d_in[6];
    const float* b0   = (const float*)d_in[7];
    int B = in_sizes[0] / 640;

    dim3 grid(5, (B + BM - 1) / BM, 1);
    tpr_kernel<<<grid, NT>>>(x, y, w000, w110, w011, w101, w111, b0,
                             (float*)d_out, B);
}

// round 4
// speedup vs baseline: 1.0553x; 1.0553x over previous
#include <cuda_runtime.h>

#define BM 128
#define BN 128
#define BK 16
#define NT 256

// Fused TensorProductRescale:
//   region 0            : out0 (N=256, K=384)  A = [x0*y0 | d],      W = [SQK0*w000 ; SQK0*IS3*w110]
//   region i (i0=0..2)  : out1[:,:,i0] (N=128, K=512)
//                         A = [x0*y1_i | x1_i*y0 | cr_i], W = [SQK1*w011 ; SQK1*w101 ; SQK1*IS2*w111]
__global__ void __launch_bounds__(NT, 2)
tpr_kernel(const float* __restrict__ x, const float* __restrict__ y,
           const float* __restrict__ w000, const float* __restrict__ w110,
           const float* __restrict__ w011, const float* __restrict__ w101,
           const float* __restrict__ w111, const float* __restrict__ b0,
           float* __restrict__ out, int B)
{
    const float SQK0 = 0.05103103630798288f;   // 1/sqrt(384)
    const float SQK1 = 0.04419417382415922f;   // 1/sqrt(512)
    const float IS3  = 0.57735026918962584f;   // 1/sqrt(3)
    const float IS2  = 0.70710678118654752f;   // 1/sqrt(2)

    __shared__ float As[BK][BM + 1];   // +1 pad: conflict-free k-strided writes
    __shared__ float Ws[BK][BN];
    __shared__ float ys[BM][4];

    const int job  = blockIdx.x;           // 0,1 -> region0 colblock; 2,3,4 -> region 1..3
    const int row0 = blockIdx.y * BM;
    const int tid  = threadIdx.x;
    const int tx   = tid & 15;             // col group (8 cols each)
    const int ty   = tid >> 4;             // row group (8 strided rows each)
    const int nb   = tx * 8;

    int region, cb;
    if (job < 2) { region = 0; cb = job; } else { region = job - 1; cb = 0; }
    const int i0 = region - 1;             // only meaningful when region > 0
    const int j1 = (i0 + 1) % 3;
    const int j2 = (i0 + 2) % 3;

    // load y tile
    for (int i = tid; i < BM * 4; i += NT) {
        int m = i >> 2, c = i & 3;
        int r = row0 + m;
        ys[m][c] = (r < B) ? y[(size_t)r * 4 + c] : 0.0f;
    }

    float acc[8][8];
    #pragma unroll
    for (int r = 0; r < 8; r++)
        #pragma unroll
        for (int c = 0; c < 8; c++) acc[r][c] = 0.0f;

    const int KT  = (region == 0) ? 24 : 32;   // K/BK
    const int fm  = tid >> 1;                  // feature row handled by this thread
    const int fkb = (tid & 1) * 8;             // feature k sub-block (0 or 8)
    const int frow = row0 + fm;
    const float* xr = x + (size_t)frow * 640;

    __syncthreads();   // ys ready

    for (int kt = 0; kt < KT; kt++) {
        const int k0 = kt * BK;

        // ---- stage weight tile (scales folded) ----
        #pragma unroll
        for (int r = 0; r < 2; r++) {
            int idx = tid + r * NT;        // float4 index within 16x128 tile
            int kw  = idx >> 5;            // 0..15
            int col = (idx & 31) * 4;
            int kg  = k0 + kw;
            const float* src; float s;
            if (region == 0) {
                if (kg < 256) { src = w000 + (size_t)kg * 256 + cb * 128 + col;        s = SQK0; }
                else          { src = w110 + (size_t)(kg - 256) * 256 + cb * 128 + col; s = SQK0 * IS3; }
            } else {
                if (kg < 256)      { src = w011 + (size_t)kg * 128 + col;         s = SQK1; }
                else if (kg < 384) { src = w101 + (size_t)(kg - 256) * 128 + col; s = SQK1; }
                else               { src = w111 + (size_t)(kg - 384) * 128 + col; s = SQK1 * IS2; }
            }
            float4 v = *(const float4*)src;
            v.x *= s; v.y *= s; v.z *= s; v.w *= s;
            *(float4*)&Ws[kw][col] = v;
        }

        // ---- stage feature tile (computed on the fly) ----
        float f[8];
        if (frow < B) {
            float yv0 = ys[fm][0], yv1 = ys[fm][1], yv2 = ys[fm][2], yv3 = ys[fm][3];
            if (k0 < 256) {
                float sc = (region == 0) ? yv0 : ys[fm][1 + i0];
                const float4* p = (const float4*)(xr + k0 + fkb);
                float4 a0 = p[0], a1 = p[1];
                f[0] = a0.x * sc; f[1] = a0.y * sc; f[2] = a0.z * sc; f[3] = a0.w * sc;
                f[4] = a1.x * sc; f[5] = a1.y * sc; f[6] = a1.z * sc; f[7] = a1.w * sc;
            } else {
                int u0, mode;                   // 0: d, 1: x1_i*y0, 2: cross
                if (region == 0)   { u0 = k0 - 256 + fkb; mode = 0; }
                else if (k0 < 384) { u0 = k0 - 256 + fkb; mode = 1; }
                else               { u0 = k0 - 384 + fkb; mode = 2; }
                const float4* p = (const float4*)(xr + 256 + 3 * u0);
                float v[24];
                #pragma unroll
                for (int q = 0; q < 6; q++) *(float4*)&v[4 * q] = p[q];
                #pragma unroll
                for (int jj = 0; jj < 8; jj++) {
                    float e0 = v[3 * jj], e1 = v[3 * jj + 1], e2 = v[3 * jj + 2];
                    if (mode == 0) {
                        f[jj] = e0 * yv1 + e1 * yv2 + e2 * yv3;          // d[u]
                    } else if (mode == 1) {
                        float xi = (i0 == 0) ? e0 : ((i0 == 1) ? e1 : e2);
                        f[jj] = xi * yv0;                                 // x1_i * y0
                    } else {
                        // cr_i = x1_{j1} * y1_{j2} - x1_{j2} * y1_{j1}
                        float xa = (j1 == 0) ? e0 : ((j1 == 1) ? e1 : e2);
                        float xb = (j2 == 0) ? e0 : ((j2 == 1) ? e1 : e2);
                        float ya = (j2 == 0) ? yv1 : ((j2 == 1) ? yv2 : yv3);
                        float yb = (j1 == 0) ? yv1 : ((j1 == 1) ? yv2 : yv3);
                        f[jj] = xa * ya - xb * yb;
                    }
                }
            }
        } else {
            #pragma unroll
            for (int jj = 0; jj < 8; jj++) f[jj] = 0.0f;
        }
        #pragma unroll
        for (int jj = 0; jj < 8; jj++) As[fkb + jj][fm] = f[jj];

        __syncthreads();

        // ---- compute ----
        #pragma unroll
        for (int k = 0; k < BK; k++) {
            float a[8];
            #pragma unroll
            for (int r = 0; r < 8; r++) a[r] = As[k][ty + 16 * r];
            float4 w0 = *(const float4*)&Ws[k][nb];
            float4 w1 = *(const float4*)&Ws[k][nb + 4];
            float w[8] = {w0.x, w0.y, w0.z, w0.w, w1.x, w1.y, w1.z, w1.w};
            #pragma unroll
            for (int r = 0; r < 8; r++)
                #pragma unroll
                for (int c = 0; c < 8; c++)
                    acc[r][c] = fmaf(a[r], w[c], acc[r][c]);
        }

        __syncthreads();
    }

    // ---- epilogue ----
    if (region == 0) {
        float4 bv0 = *(const float4*)&b0[cb * 128 + nb];
        float4 bv1 = *(const float4*)&b0[cb * 128 + nb + 4];
        #pragma unroll
        for (int r = 0; r < 8; r++) {
            int row = row0 + ty + 16 * r;
            if (row < B) {
                float* o = out + (size_t)row * 640 + cb * 128 + nb;
                float4 s0 = make_float4(acc[r][0] + bv0.x, acc[r][1] + bv0.y,
                                        acc[r][2] + bv0.z, acc[r][3] + bv0.w);
                float4 s1 = make_float4(acc[r][4] + bv1.x, acc[r][5] + bv1.y,
                                        acc[r][6] + bv1.z, acc[r][7] + bv1.w);
                *(float4*)o       = s0;
                *(float4*)(o + 4) = s1;
            }
        }
    } else {
        #pragma unroll
        for (int r = 0; r < 8; r++) {
            int row = row0 + ty + 16 * r;
            if (row < B) {
                float* o = out + (size_t)row * 640 + 256 + i0;
                #pragma unroll
                for (int c = 0; c < 8; c++)
                    o[(nb + c) * 3] = acc[r][c];   // out1 layout: 256 + w*3 + i
            }
        }
    }
}

extern "C" void kernel_launch(void* const* d_in, const int* in_sizes, int n_in,
                              void* d_out, int out_size)
{
    const float* x    = (const float*)d_in[0];
    const float* y    = (const float*)d_in[1];
    const float* w000 = (const float*)d_in[2];
    const float* w110 = (const float*)d_in[3];
    const float* w011 = (const float*)d_in[4];
    const float* w101 = (const float*)d_in[5];
    const float* w111 = (const float*)d_in[6];
    const float* b0   = (const float*)d_in[7];
    int B = in_sizes[0] / 640;

    dim3 grid(5, (B + BM - 1) / BM, 1);
    tpr_kernel<<<grid, NT>>>(x, y, w000, w110, w011, w101, w111, b0,
                             (float*)d_out, B);
}